// round 2
// baseline (speedup 1.0000x reference)
#include <cuda_runtime.h>
#include <math.h>

#define BB 8
#define LL 2048
#define WW 1024
#define KK 5
#define GG 2
#define CI 512            // in channels per group
#define CO 512            // out channels per group
#define RDIM (KK*CI)      // 2560 reduction dim per group

// ---- static scratch (no allocations allowed) ----
__device__ float g_wT[GG*KK*CI*CO];   // conv_w transposed: [g][k][c][o], 10 MB
__device__ int   g_p0[BB*LL*KK];
__device__ float g_frac[BB*LL*KK];
__device__ float g_h[(size_t)BB*LL*WW]; // conv output, 64 MB
__device__ float g_s[BB*LL];          // per-row projected scalar

// ============================================================
// Kernel 1: transpose conv_w [g][o][c][k] -> g_wT [g][k][c][o]
// ============================================================
__global__ void transpose_w_kernel(const float* __restrict__ conv_w) {
    int idx = blockIdx.x * 256 + threadIdx.x;
    if (idx >= GG*KK*CI*CO) return;
    int o = idx % CO;
    int c = (idx / CO) % CI;
    int k = (idx / (CO*CI)) % KK;
    int g = idx / (CO*CI*KK);
    g_wT[idx] = conv_w[(((g*CO + o)*CI + c)*KK) + k];
}

// ============================================================
// Kernel 2: offsets = tanh(x @ w_off + b_off) * 2 -> (p0, frac)
// one block of 128 threads per (b,l) row
// ============================================================
__global__ void offsets_kernel(const float* __restrict__ x,
                               const float* __restrict__ w_off,
                               const float* __restrict__ b_off) {
    int row = blockIdx.x;                 // b*LL + l
    int tid = threadIdx.x;                // 128
    const float* xr = x + (size_t)row * WW;
    float acc[KK] = {0.f, 0.f, 0.f, 0.f, 0.f};
    for (int w = tid; w < WW; w += 128) {
        float xv = xr[w];
        #pragma unroll
        for (int k = 0; k < KK; k++) acc[k] += xv * w_off[w*KK + k];
    }
    __shared__ float sh[KK][128];
    #pragma unroll
    for (int k = 0; k < KK; k++) sh[k][tid] = acc[k];
    __syncthreads();
    for (int s = 64; s > 0; s >>= 1) {
        if (tid < s) {
            #pragma unroll
            for (int k = 0; k < KK; k++) sh[k][tid] += sh[k][tid + s];
        }
        __syncthreads();
    }
    if (tid < KK) {
        int k = tid;
        float off = tanhf(sh[k][0] + b_off[k]) * 2.0f;
        int l = row & (LL - 1);
        float pos = (float)l + ((float)k - 2.0f) + off;
        float p0 = floorf(pos);
        g_p0[row*KK + k]   = (int)p0;
        g_frac[row*KK + k] = pos - p0;
    }
}

// ============================================================
// Kernel 3: deformable grouped conv as gathered GEMM (fp32)
// per group g: out[m, n] = sum_r A[m, r] * Bw[r, n]
//   m = b*LL + l (16384), n = out channel in group (512), r = k*CI + c (2560)
//   A[m, k*CI+c] = lerp(x[b, p0(m,k), g*CI+c], x[b, p0+1, ...], frac) w/ zero pad
// Tile: 128x128, KC=8, 256 threads, 8x8 per thread.
// ============================================================
#define MT 128
#define NT 128
#define KC 8

__global__ __launch_bounds__(256, 2)
void conv_kernel(const float* __restrict__ x) {
    __shared__ __align__(16) float As[KC][MT];
    __shared__ __align__(16) float Bs[KC][NT];

    int bx = blockIdx.x;                 // 8 = GG * (CO/NT)
    int g  = bx >> 2;
    int n_base = (bx & 3) * NT;
    int m_base = blockIdx.y * MT;
    int tid = threadIdx.x;

    // A-load mapping: each thread loads 4 consecutive r for one m
    int la_m = tid >> 1;                 // 0..127
    int la_r = (tid & 1) * 4;            // 0 or 4
    int mg = m_base + la_m;              // = b*LL + l (tiles never straddle b)
    int b  = mg >> 11;
    const float* xb = x + ((size_t)b * LL) * WW + g * CI;
    const int*   p0p = &g_p0[mg * KK];
    const float* frp = &g_frac[mg * KK];

    // B-load mapping
    int lb_r = tid >> 5;                 // 0..7
    int lb_n = (tid & 31) * 4;

    int tx = tid & 15, ty = tid >> 4;

    float acc[8][8];
    #pragma unroll
    for (int i = 0; i < 8; i++)
        #pragma unroll
        for (int j = 0; j < 8; j++) acc[i][j] = 0.f;

    const float* wTg = &g_wT[(size_t)g * RDIM * CO + n_base];

    for (int ch = 0; ch < RDIM / KC; ch++) {
        int r0 = ch * KC;
        // ---- load A tile (gather + lerp) ----
        {
            int rg = r0 + la_r;
            int k  = rg / CI;            // constant across the 4 elems (CI%8==0)
            int c  = rg % CI;            // multiple of 4
            int p0 = p0p[k];
            float f = frp[k];
            float4 v0 = make_float4(0.f, 0.f, 0.f, 0.f);
            float4 v1 = make_float4(0.f, 0.f, 0.f, 0.f);
            if (p0 >= 0 && p0 < LL)
                v0 = *(const float4*)(xb + (size_t)p0 * WW + c);
            int p1 = p0 + 1;
            if (p1 >= 0 && p1 < LL)
                v1 = *(const float4*)(xb + (size_t)p1 * WW + c);
            float w1 = f, w0 = 1.0f - f;
            As[la_r + 0][la_m] = v0.x * w0 + v1.x * w1;
            As[la_r + 1][la_m] = v0.y * w0 + v1.y * w1;
            As[la_r + 2][la_m] = v0.z * w0 + v1.z * w1;
            As[la_r + 3][la_m] = v0.w * w0 + v1.w * w1;
        }
        // ---- load B tile ----
        {
            float4 bv = *(const float4*)(wTg + (size_t)(r0 + lb_r) * CO + lb_n);
            *(float4*)&Bs[lb_r][lb_n] = bv;
        }
        __syncthreads();
        // ---- compute ----
        #pragma unroll
        for (int rk = 0; rk < KC; rk++) {
            float a[8], bv[8];
            *(float4*)&a[0]  = *(const float4*)&As[rk][ty * 8];
            *(float4*)&a[4]  = *(const float4*)&As[rk][ty * 8 + 4];
            *(float4*)&bv[0] = *(const float4*)&Bs[rk][tx * 8];
            *(float4*)&bv[4] = *(const float4*)&Bs[rk][tx * 8 + 4];
            #pragma unroll
            for (int i = 0; i < 8; i++)
                #pragma unroll
                for (int j = 0; j < 8; j++)
                    acc[i][j] = fmaf(a[i], bv[j], acc[i][j]);
        }
        __syncthreads();
    }

    // ---- epilogue: store to g_h ----
    #pragma unroll
    for (int i = 0; i < 8; i++) {
        int mrow = m_base + ty * 8 + i;
        float* hp = &g_h[(size_t)mrow * WW + g * CO + n_base + tx * 8];
        *(float4*)hp       = *(float4*)&acc[i][0];
        *(float4*)(hp + 4) = *(float4*)&acc[i][4];
    }
}

// ============================================================
// Kernel 4: per-row LayerNorm + mask + projection dot
// one block of 256 threads per (b,l)
// mask read as int32 (bool inputs arrive as int32; also works for f32 bits)
// ============================================================
__global__ void ln_proj_kernel(const float* __restrict__ conv_b,
                               const float* __restrict__ gamma,
                               const float* __restrict__ beta,
                               const float* __restrict__ proj_w,
                               const int* __restrict__ mask) {
    int row = blockIdx.x;
    int tid = threadIdx.x;   // 256
    const float* hr = &g_h[(size_t)row * WW];

    float v[4];
    float s = 0.f, ss = 0.f;
    #pragma unroll
    for (int i = 0; i < 4; i++) {
        int w = tid + i * 256;
        float hv = hr[w] + conv_b[w];
        v[i] = hv;
        s  += hv;
        ss += hv * hv;
    }
    // block reduce s, ss
    __shared__ float shA[8], shB[8];
    __shared__ float mu_sh, rstd_sh;
    #pragma unroll
    for (int o = 16; o > 0; o >>= 1) {
        s  += __shfl_xor_sync(0xffffffff, s,  o);
        ss += __shfl_xor_sync(0xffffffff, ss, o);
    }
    int warp = tid >> 5, lane = tid & 31;
    if (lane == 0) { shA[warp] = s; shB[warp] = ss; }
    __syncthreads();
    if (tid == 0) {
        float S = 0.f, SS = 0.f;
        #pragma unroll
        for (int i = 0; i < 8; i++) { S += shA[i]; SS += shB[i]; }
        float mu = S / (float)WW;
        float var = SS / (float)WW - mu * mu;
        mu_sh = mu;
        rstd_sh = rsqrtf(var + 1e-5f);
    }
    __syncthreads();
    float mu = mu_sh, rstd = rstd_sh;

    float dot = 0.f;
    #pragma unroll
    for (int i = 0; i < 4; i++) {
        int w = tid + i * 256;
        dot += ((v[i] - mu) * rstd * gamma[w] + beta[w]) * proj_w[w];
    }
    #pragma unroll
    for (int o = 16; o > 0; o >>= 1)
        dot += __shfl_xor_sync(0xffffffff, dot, o);
    __syncthreads();
    if (lane == 0) shA[warp] = dot;
    __syncthreads();
    if (tid == 0) {
        float D = 0.f;
        #pragma unroll
        for (int i = 0; i < 8; i++) D += shA[i];
        g_s[row] = (mask[row] != 0) ? 0.f : D;
    }
}

// ============================================================
// Kernel 5: final masked mean over L + proj_b
// ============================================================
__global__ void final_kernel(const int* __restrict__ mask,
                             const float* __restrict__ proj_b,
                             float* __restrict__ out) {
    int b = blockIdx.x;
    int tid = threadIdx.x;  // 256
    float s = 0.f;
    int cnt = 0;
    for (int l = tid; l < LL; l += 256) {
        s += g_s[b * LL + l];
        cnt += (mask[b * LL + l] != 0) ? 0 : 1;
    }
    #pragma unroll
    for (int o = 16; o > 0; o >>= 1) {
        s   += __shfl_xor_sync(0xffffffff, s, o);
        cnt += __shfl_xor_sync(0xffffffff, cnt, o);
    }
    __shared__ float shS[8];
    __shared__ int   shC[8];
    int warp = tid >> 5, lane = tid & 31;
    if (lane == 0) { shS[warp] = s; shC[warp] = cnt; }
    __syncthreads();
    if (tid == 0) {
        float S = 0.f; int C = 0;
        #pragma unroll
        for (int i = 0; i < 8; i++) { S += shS[i]; C += shC[i]; }
        float len = fmaxf((float)C, 1.0f);
        out[b] = S / len + proj_b[0];
    }
}

// ============================================================
extern "C" void kernel_launch(void* const* d_in, const int* in_sizes, int n_in,
                              void* d_out, int out_size) {
    const float* x       = (const float*)d_in[0];
    const int*   mask    = (const int*)d_in[1];
    const float* w_off   = (const float*)d_in[2];
    const float* b_off   = (const float*)d_in[3];
    const float* conv_w  = (const float*)d_in[4];
    const float* conv_b  = (const float*)d_in[5];
    const float* gamma   = (const float*)d_in[6];
    const float* beta    = (const float*)d_in[7];
    const float* proj_w  = (const float*)d_in[8];
    const float* proj_b  = (const float*)d_in[9];
    float* out = (float*)d_out;

    transpose_w_kernel<<<(GG*KK*CI*CO + 255) / 256, 256>>>(conv_w);
    offsets_kernel<<<BB * LL, 128>>>(x, w_off, b_off);
    dim3 cgrid(GG * (CO / NT), (BB * LL) / MT);   // (8, 128)
    conv_kernel<<<cgrid, 256>>>(x);
    ln_proj_kernel<<<BB * LL, 256>>>(conv_b, gamma, beta, proj_w, mask);
    final_kernel<<<BB, 256>>>(mask, proj_b, out);
}

// round 6
// speedup vs baseline: 4.2232x; 4.2232x over previous
#include <cuda_runtime.h>
#include <cuda_bf16.h>
#include <math.h>
#include <stdint.h>

#define BB 8
#define LL 2048
#define WW 1024
#define KK 5
#define GG 2
#define CI 512
#define CO 512
#define RDIM (KK*CI)        // 2560

// GEMM tiling
#define MT   128            // M per CTA
#define NTT  128            // N per CTA
#define KCB  32             // K-chunk in bf16 elems (64B rows)
#define NCH  (RDIM/KCB)     // 80 chunks

// ---- static scratch ----
__device__ __nv_bfloat16 g_Bhi[GG*CO*RDIM];   // [g][o][r] K-major
__device__ __nv_bfloat16 g_Blo[GG*CO*RDIM];
__device__ int   g_p0[BB*LL*KK];
__device__ float g_frac[BB*LL*KK];
__device__ float g_h[(size_t)BB*LL*WW];       // conv output, 64 MB
__device__ float g_s[BB*LL];

// ============================================================
__device__ __forceinline__ uint32_t smem_u32(const void* p) {
    uint32_t a;
    asm("{ .reg .u64 t; cvta.to.shared.u64 t, %1; cvt.u32.u64 %0, t; }" : "=r"(a) : "l"(p));
    return a;
}
#define LDSM4(r, addr) \
    asm volatile("ldmatrix.sync.aligned.m8n8.x4.shared.b16 {%0,%1,%2,%3}, [%4];" \
        : "=r"((r)[0]), "=r"((r)[1]), "=r"((r)[2]), "=r"((r)[3]) : "r"(addr))
#define MMA16816(d, a, b0, b1) \
    asm volatile("mma.sync.aligned.m16n8k16.row.col.f32.bf16.bf16.f32 " \
        "{%0,%1,%2,%3}, {%4,%5,%6,%7}, {%8,%9}, {%0,%1,%2,%3};" \
        : "+f"((d)[0]), "+f"((d)[1]), "+f"((d)[2]), "+f"((d)[3]) \
        : "r"((a)[0]), "r"((a)[1]), "r"((a)[2]), "r"((a)[3]), "r"(b0), "r"(b1))

// ============================================================
// Kernel 1: B prep — conv_w [g][o][c][k] -> bf16 hi/lo [g][o][r=k*CI+c]
// ============================================================
__global__ void prep_b_kernel(const float* __restrict__ conv_w) {
    int idx = blockIdx.x * 256 + threadIdx.x;
    if (idx >= GG*CO*RDIM) return;
    int r = idx % RDIM;
    int o = (idx / RDIM) % CO;
    int g = idx / (RDIM*CO);
    int k = r / CI, c = r % CI;
    float w = conv_w[(((g*CO + o)*CI + c)*KK) + k];
    __nv_bfloat16 hi = __float2bfloat16(w);
    __nv_bfloat16 lo = __float2bfloat16(w - __bfloat162float(hi));
    g_Bhi[idx] = hi;
    g_Blo[idx] = lo;
}

// ============================================================
// Kernel 2: offsets
// ============================================================
__global__ void offsets_kernel(const float* __restrict__ x,
                               const float* __restrict__ w_off,
                               const float* __restrict__ b_off) {
    int row = blockIdx.x;
    int tid = threadIdx.x;                // 128
    const float* xr = x + (size_t)row * WW;
    float acc[KK] = {0.f, 0.f, 0.f, 0.f, 0.f};
    for (int w = tid; w < WW; w += 128) {
        float xv = xr[w];
        #pragma unroll
        for (int k = 0; k < KK; k++) acc[k] += xv * w_off[w*KK + k];
    }
    __shared__ float sh[KK][128];
    #pragma unroll
    for (int k = 0; k < KK; k++) sh[k][tid] = acc[k];
    __syncthreads();
    for (int s = 64; s > 0; s >>= 1) {
        if (tid < s) {
            #pragma unroll
            for (int k = 0; k < KK; k++) sh[k][tid] += sh[k][tid + s];
        }
        __syncthreads();
    }
    if (tid < KK) {
        int k = tid;
        float off = tanhf(sh[k][0] + b_off[k]) * 2.0f;
        int l = row & (LL - 1);
        float pos = (float)l + ((float)k - 2.0f) + off;
        float p0 = floorf(pos);
        g_p0[row*KK + k]   = (int)p0;
        g_frac[row*KK + k] = pos - p0;
    }
}

// ============================================================
// Kernel 3: split-bf16 HMMA gathered GEMM
// grid (GG*4, 128); 512 threads = 16 warps (4m x 4n), warp tile 32x32
// SMEM stage (32KB): A_hi 8K | A_lo 8K | B_hi 8K | B_lo 8K; 2 stages
// Tiles are 128 rows x 64B (32 bf16), swizzle: grp16 ^= (row>>1)&3
// ============================================================
#define SA_HI(s) ((s)*32768 + 0)
#define SA_LO(s) ((s)*32768 + 8192)
#define SB_HI(s) ((s)*32768 + 16384)
#define SB_LO(s) ((s)*32768 + 24576)
#define SMEM_CONV (2*32768)

__global__ void __launch_bounds__(512) conv_mma_kernel(const float* __restrict__ x) {
    extern __shared__ __align__(128) char smem[];
    const uint32_t sb = smem_u32(smem);

    const int tid  = threadIdx.x;
    const int lane = tid & 31;
    const int wid  = tid >> 5;

    const int g      = blockIdx.x >> 2;
    const int n_base = (blockIdx.x & 3) * NTT;
    const int m_base = blockIdx.y * MT;

    // ---- loader mapping: thread t -> (row = t>>2, 8-col group = t&3) ----
    const int lrow = tid >> 2;
    const int lgrp = tid & 3;
    const int mg   = m_base + lrow;
    const float* xb = x + ((size_t)(mg >> 11)) * LL * WW + g * CI + lgrp * 8;
    const int*   p0p = &g_p0[mg * KK];
    const float* frp = &g_frac[mg * KK];
    const size_t gBrow = (size_t)(g * CO + n_base + lrow) * RDIM + lgrp * 8;
    const uint32_t offST = (uint32_t)(lrow * 64 + ((lgrp ^ ((lrow >> 1) & 3)) << 4));

    // ---- compute mapping ----
    const int wm = (wid & 3) * 32;       // warp m offset
    const int wn = (wid >> 2) * 32;      // warp n offset
    const int rA0 = wm + (lane & 15), rA1 = rA0 + 16;
    const int rB0 = wn + (lane & 15), rB1 = rB0 + 16;
    const int sA0 = (rA0 >> 1) & 3, sA1 = (rA1 >> 1) & 3;
    const int sB0 = (rB0 >> 1) & 3, sB1 = (rB1 >> 1) & 3;
    const int hi16 = lane >> 4;          // 0/1 -> +16B within k

    float acc[2][4][4];
    #pragma unroll
    for (int mi = 0; mi < 2; mi++)
        #pragma unroll
        for (int nt = 0; nt < 4; nt++)
            #pragma unroll
            for (int e = 0; e < 4; e++) acc[mi][nt][e] = 0.f;

    // staging registers
    float4 a00, a01, a10, a11;
    uint4 bhv, blv;
    float lfrac;
    int   lok0, lok1;

    // ---- load chunk ch into staging regs ----
    auto LOADG = [&](int ch) {
        int ktap = ch >> 4;
        int c0   = (ch & 15) * KCB;
        int p0   = p0p[ktap];
        lfrac    = frp[ktap];
        lok0 = (p0 >= 0) & (p0 < LL);
        lok1 = (p0 >= -1) & (p0 < LL - 1);
        const float* pa = xb + c0 + (size_t)p0 * WW;
        float4 z = make_float4(0.f, 0.f, 0.f, 0.f);
        a00 = z; a01 = z; a10 = z; a11 = z;
        if (lok0) { a00 = *(const float4*)(pa);      a01 = *(const float4*)(pa + 4); }
        if (lok1) { a10 = *(const float4*)(pa + WW); a11 = *(const float4*)(pa + WW + 4); }
        bhv = *(const uint4*)(g_Bhi + gBrow + ch * KCB);
        blv = *(const uint4*)(g_Blo + gBrow + ch * KCB);
    };

    // ---- convert staging regs and store to stage s ----
    auto STORES = [&](int s) {
        float w0 = 1.0f - lfrac, w1 = lfrac;
        float v[8];
        v[0] = a00.x*w0 + a10.x*w1; v[1] = a00.y*w0 + a10.y*w1;
        v[2] = a00.z*w0 + a10.z*w1; v[3] = a00.w*w0 + a10.w*w1;
        v[4] = a01.x*w0 + a11.x*w1; v[5] = a01.y*w0 + a11.y*w1;
        v[6] = a01.z*w0 + a11.z*w1; v[7] = a01.w*w0 + a11.w*w1;
        __nv_bfloat16 hv[8], lv[8];
        #pragma unroll
        for (int e = 0; e < 8; e++) {
            hv[e] = __float2bfloat16(v[e]);
            lv[e] = __float2bfloat16(v[e] - __bfloat162float(hv[e]));
        }
        *(uint4*)(smem + SA_HI(s) + offST) = *(uint4*)hv;
        *(uint4*)(smem + SA_LO(s) + offST) = *(uint4*)lv;
        *(uint4*)(smem + SB_HI(s) + offST) = bhv;
        *(uint4*)(smem + SB_LO(s) + offST) = blv;
    };

    // ---- compute on stage s ----
    auto COMPUTE = [&](int s) {
        const uint32_t bAhi = sb + SA_HI(s), bAlo = sb + SA_LO(s);
        const uint32_t bBhi = sb + SB_HI(s), bBlo = sb + SB_LO(s);
        #pragma unroll
        for (int ks = 0; ks < 2; ks++) {
            const int grp = ks * 2 + hi16;
            const uint32_t oA0 = (uint32_t)(rA0 * 64 + ((grp ^ sA0) << 4));
            const uint32_t oA1 = (uint32_t)(rA1 * 64 + ((grp ^ sA1) << 4));
            const uint32_t oB0 = (uint32_t)(rB0 * 64 + ((grp ^ sB0) << 4));
            const uint32_t oB1 = (uint32_t)(rB1 * 64 + ((grp ^ sB1) << 4));
            uint32_t ah0[4], ah1[4], al0[4], al1[4];
            uint32_t bh0[4], bh1[4], bl0[4], bl1[4];
            LDSM4(ah0, bAhi + oA0);  LDSM4(ah1, bAhi + oA1);
            LDSM4(bh0, bBhi + oB0);  LDSM4(bh1, bBhi + oB1);
            LDSM4(al0, bAlo + oA0);  LDSM4(al1, bAlo + oA1);
            LDSM4(bl0, bBlo + oB0);  LDSM4(bl1, bBlo + oB1);
            // hi*hi
            MMA16816(acc[0][0], ah0, bh0[0], bh0[2]);
            MMA16816(acc[0][1], ah0, bh0[1], bh0[3]);
            MMA16816(acc[0][2], ah0, bh1[0], bh1[2]);
            MMA16816(acc[0][3], ah0, bh1[1], bh1[3]);
            MMA16816(acc[1][0], ah1, bh0[0], bh0[2]);
            MMA16816(acc[1][1], ah1, bh0[1], bh0[3]);
            MMA16816(acc[1][2], ah1, bh1[0], bh1[2]);
            MMA16816(acc[1][3], ah1, bh1[1], bh1[3]);
            // hi*lo
            MMA16816(acc[0][0], ah0, bl0[0], bl0[2]);
            MMA16816(acc[0][1], ah0, bl0[1], bl0[3]);
            MMA16816(acc[0][2], ah0, bl1[0], bl1[2]);
            MMA16816(acc[0][3], ah0, bl1[1], bl1[3]);
            MMA16816(acc[1][0], ah1, bl0[0], bl0[2]);
            MMA16816(acc[1][1], ah1, bl0[1], bl0[3]);
            MMA16816(acc[1][2], ah1, bl1[0], bl1[2]);
            MMA16816(acc[1][3], ah1, bl1[1], bl1[3]);
            // lo*hi
            MMA16816(acc[0][0], al0, bh0[0], bh0[2]);
            MMA16816(acc[0][1], al0, bh0[1], bh0[3]);
            MMA16816(acc[0][2], al0, bh1[0], bh1[2]);
            MMA16816(acc[0][3], al0, bh1[1], bh1[3]);
            MMA16816(acc[1][0], al1, bh0[0], bh0[2]);
            MMA16816(acc[1][1], al1, bh0[1], bh0[3]);
            MMA16816(acc[1][2], al1, bh1[0], bh1[2]);
            MMA16816(acc[1][3], al1, bh1[1], bh1[3]);
        }
    };

    // ---- pipeline ----
    LOADG(0);
    STORES(0);
    __syncthreads();
    int s = 0;
    for (int ch = 0; ch < NCH; ch++) {
        if (ch + 1 < NCH) LOADG(ch + 1);
        COMPUTE(s);
        if (ch + 1 < NCH) STORES(s ^ 1);
        __syncthreads();
        s ^= 1;
    }

    // ---- epilogue: write accum -> g_h ----
    const int gcol = g * CO + n_base + wn;
    const int r    = lane >> 2;
    const int c    = (lane & 3) * 2;
    #pragma unroll
    for (int mi = 0; mi < 2; mi++) {
        int m = m_base + wm + mi * 16 + r;
        #pragma unroll
        for (int nt = 0; nt < 4; nt++) {
            int n = gcol + nt * 8 + c;
            float2 v0 = make_float2(acc[mi][nt][0], acc[mi][nt][1]);
            float2 v1 = make_float2(acc[mi][nt][2], acc[mi][nt][3]);
            *(float2*)&g_h[(size_t)m * WW + n]       = v0;
            *(float2*)&g_h[(size_t)(m + 8) * WW + n] = v1;
        }
    }
}

// ============================================================
// Kernel 4: per-row LayerNorm + mask + projection dot
// ============================================================
__global__ void ln_proj_kernel(const float* __restrict__ conv_b,
                               const float* __restrict__ gamma,
                               const float* __restrict__ beta,
                               const float* __restrict__ proj_w,
                               const int* __restrict__ mask) {
    int row = blockIdx.x;
    int tid = threadIdx.x;   // 256
    const float* hr = &g_h[(size_t)row * WW];

    float v[4];
    float s = 0.f, ss = 0.f;
    #pragma unroll
    for (int i = 0; i < 4; i++) {
        int w = tid + i * 256;
        float hv = hr[w] + conv_b[w];
        v[i] = hv;
        s  += hv;
        ss += hv * hv;
    }
    __shared__ float shA[8], shB[8];
    __shared__ float mu_sh, rstd_sh;
    #pragma unroll
    for (int o = 16; o > 0; o >>= 1) {
        s  += __shfl_xor_sync(0xffffffff, s,  o);
        ss += __shfl_xor_sync(0xffffffff, ss, o);
    }
    int warp = tid >> 5, lane = tid & 31;
    if (lane == 0) { shA[warp] = s; shB[warp] = ss; }
    __syncthreads();
    if (tid == 0) {
        float S = 0.f, SS = 0.f;
        #pragma unroll
        for (int i = 0; i < 8; i++) { S += shA[i]; SS += shB[i]; }
        float mu = S / (float)WW;
        float var = SS / (float)WW - mu * mu;
        mu_sh = mu;
        rstd_sh = rsqrtf(var + 1e-5f);
    }
    __syncthreads();
    float mu = mu_sh, rstd = rstd_sh;

    float dot = 0.f;
    #pragma unroll
    for (int i = 0; i < 4; i++) {
        int w = tid + i * 256;
        dot += ((v[i] - mu) * rstd * gamma[w] + beta[w]) * proj_w[w];
    }
    #pragma unroll
    for (int o = 16; o > 0; o >>= 1)
        dot += __shfl_xor_sync(0xffffffff, dot, o);
    __syncthreads();
    if (lane == 0) shA[warp] = dot;
    __syncthreads();
    if (tid == 0) {
        float D = 0.f;
        #pragma unroll
        for (int i = 0; i < 8; i++) D += shA[i];
        g_s[row] = (mask[row] != 0) ? 0.f : D;
    }
}

// ============================================================
// Kernel 5: final masked mean over L + proj_b
// ============================================================
__global__ void final_kernel(const int* __restrict__ mask,
                             const float* __restrict__ proj_b,
                             float* __restrict__ out) {
    int b = blockIdx.x;
    int tid = threadIdx.x;  // 256
    float s = 0.f;
    int cnt = 0;
    for (int l = tid; l < LL; l += 256) {
        s += g_s[b * LL + l];
        cnt += (mask[b * LL + l] != 0) ? 0 : 1;
    }
    #pragma unroll
    for (int o = 16; o > 0; o >>= 1) {
        s   += __shfl_xor_sync(0xffffffff, s, o);
        cnt += __shfl_xor_sync(0xffffffff, cnt, o);
    }
    __shared__ float shS[8];
    __shared__ int   shC[8];
    int warp = tid >> 5, lane = tid & 31;
    if (lane == 0) { shS[warp] = s; shC[warp] = cnt; }
    __syncthreads();
    if (tid == 0) {
        float S = 0.f; int C = 0;
        #pragma unroll
        for (int i = 0; i < 8; i++) { S += shS[i]; C += shC[i]; }
        float len = fmaxf((float)C, 1.0f);
        out[b] = S / len + proj_b[0];
    }
}

// ============================================================
extern "C" void kernel_launch(void* const* d_in, const int* in_sizes, int n_in,
                              void* d_out, int out_size) {
    const float* x       = (const float*)d_in[0];
    const int*   mask    = (const int*)d_in[1];
    const float* w_off   = (const float*)d_in[2];
    const float* b_off   = (const float*)d_in[3];
    const float* conv_w  = (const float*)d_in[4];
    const float* conv_b  = (const float*)d_in[5];
    const float* gamma   = (const float*)d_in[6];
    const float* beta    = (const float*)d_in[7];
    const float* proj_w  = (const float*)d_in[8];
    const float* proj_b  = (const float*)d_in[9];
    float* out = (float*)d_out;

    cudaFuncSetAttribute(conv_mma_kernel,
                         cudaFuncAttributeMaxDynamicSharedMemorySize, SMEM_CONV);

    prep_b_kernel<<<(GG*CO*RDIM + 255) / 256, 256>>>(conv_w);
    offsets_kernel<<<BB * LL, 128>>>(x, w_off, b_off);
    dim3 cgrid(GG * 4, (BB * LL) / MT);   // (8, 128)
    conv_mma_kernel<<<cgrid, 512, SMEM_CONV>>>(x);
    ln_proj_kernel<<<BB * LL, 256>>>(conv_b, gamma, beta, proj_w, mask);
    final_kernel<<<BB, 256>>>(mask, proj_b, out);
}